// round 4
// baseline (speedup 1.0000x reference)
#include <cuda_runtime.h>
#include <cuda_bf16.h>
#include <cstdint>

#define DIMG 784
#define HENC 50
#define DZ   25
#define HDEC 100

#define TM       128
#define NTHREADS 256

// Decoder weights, block-interleaved for mma B operand:
// 49 blocks x 32 rows (rows 0..15 = W_mu_d[blk*16+r][:], rows 16..31 = W_ls_d) x 112 k (k>=100 zero)
__device__ __align__(16) __nv_bfloat16 g_Wd[49 * 32 * 112];

__global__ void prep_wd(const float* __restrict__ Wmu, const float* __restrict__ Wls) {
    int idx = blockIdx.x * 256 + threadIdx.x;
    if (idx >= 49 * 32 * 112) return;
    int k   = idx % 112;
    int r   = (idx / 112) % 32;
    int blk = idx / (112 * 32);
    float v = 0.f;
    if (k < 100) {
        int j = blk * 16 + (r & 15);
        v = (r < 16) ? Wmu[j * 100 + k] : Wls[j * 100 + k];
    }
    g_Wd[idx] = __float2bfloat16(v);
}

__device__ __forceinline__ void mma16816(float* d,
                                         uint32_t a0, uint32_t a1, uint32_t a2, uint32_t a3,
                                         uint32_t b0, uint32_t b1) {
    asm volatile(
        "mma.sync.aligned.m16n8k16.row.col.f32.bf16.bf16.f32 "
        "{%0,%1,%2,%3}, {%4,%5,%6,%7}, {%8,%9}, {%0,%1,%2,%3};\n"
        : "+f"(d[0]), "+f"(d[1]), "+f"(d[2]), "+f"(d[3])
        : "r"(a0), "r"(a1), "r"(a2), "r"(a3), "r"(b0), "r"(b1));
}

// ---- shared memory layout (bytes) ----
// Region A: W1 (encoder weight, bf16 [56][792]) ; later reused as decoder B tiles (double-buffered)
#define OFF_W1  0          // 88704 bytes
// Region B: x chunk bf16 [128][120] ; later reused as hd bf16 [128][120]
#define OFF_X   88704      // 30720
#define OFF_H   119424     // h fp32 [128][52] = 26624
#define OFF_Z   146048     // z fp32 [128][28] = 14336
#define OFF_W3  160384     // W_in_d fp32 [100][28] = 11200
#define OFF_WMU 171584     // W_mu_e fp32 [25][52] = 5200
#define OFF_WLS 176784     // W_ls_e fp32 [25][52] = 5200
#define OFF_B1  181984     // fp32[56]
#define OFF_B2M 182208     // fp32[25]
#define OFF_B2L 182320     // fp32[25]
#define OFF_B3  182432     // fp32[100]
#define OFF_BMU 182848     // fp32[784]
#define OFF_BLS 185984     // fp32[784]
#define SMEM_TOTAL 189120

__global__ void __launch_bounds__(NTHREADS, 1) vae_fused(
    const float* __restrict__ x,    const float* __restrict__ epsz, const float* __restrict__ epsx,
    const float* __restrict__ W1g,  const float* __restrict__ b1g,
    const float* __restrict__ Wmug, const float* __restrict__ b2mug,
    const float* __restrict__ Wlsg, const float* __restrict__ b2lsg,
    const float* __restrict__ W3g,  const float* __restrict__ b3g,
    const float* __restrict__ bmudg, const float* __restrict__ blsdg,
    float* __restrict__ out, int Btotal)
{
    extern __shared__ char sm[];
    __nv_bfloat16* W1s = (__nv_bfloat16*)(sm + OFF_W1);
    __nv_bfloat16* xs  = (__nv_bfloat16*)(sm + OFF_X);
    __nv_bfloat16* hds = (__nv_bfloat16*)(sm + OFF_X);    // alias (after GEMM1)
    float* hs   = (float*)(sm + OFF_H);
    float* zs   = (float*)(sm + OFF_Z);
    float* W3s  = (float*)(sm + OFF_W3);
    float* Wmus = (float*)(sm + OFF_WMU);
    float* Wlss = (float*)(sm + OFF_WLS);
    float* b1s  = (float*)(sm + OFF_B1);
    float* b2ms = (float*)(sm + OFF_B2M);
    float* b2ls = (float*)(sm + OFF_B2L);
    float* b3s  = (float*)(sm + OFF_B3);
    float* bmus = (float*)(sm + OFF_BMU);
    float* blss = (float*)(sm + OFF_BLS);
    // decoder B tile double buffer (aliases W1 region after GEMM1). 7680 B each.
    __nv_bfloat16* Bbuf0 = (__nv_bfloat16*)(sm + OFF_W1);
    __nv_bfloat16* Bbuf1 = (__nv_bfloat16*)(sm + OFF_W1 + 8192);

    const int tid  = threadIdx.x;
    const int lane = tid & 31;
    const int warp = tid >> 5;
    const int row0 = blockIdx.x * TM;
    if (row0 >= Btotal) return;

    // ---- zero padded regions, then fill persistent smem ----
    for (int i = tid; i < 88704 / 16; i += NTHREADS)
        ((uint4*)(sm + OFF_W1))[i] = make_uint4(0, 0, 0, 0);
    for (int i = tid; i < (SMEM_TOTAL - OFF_W3) / 16; i += NTHREADS)
        ((uint4*)(sm + OFF_W3))[i] = make_uint4(0, 0, 0, 0);
    __syncthreads();

    for (int i = tid; i < HENC * 196; i += NTHREADS) {   // W1 [50][784] -> bf16 [56][792]
        int r = i / 196, c = (i % 196) * 4;
        float4 v = *(const float4*)&W1g[r * DIMG + c];
        __nv_bfloat162* dst = (__nv_bfloat162*)&W1s[r * 792 + c];
        dst[0] = __floats2bfloat162_rn(v.x, v.y);
        dst[1] = __floats2bfloat162_rn(v.z, v.w);
    }
    for (int i = tid; i < HDEC * DZ; i += NTHREADS) W3s[(i / DZ) * 28 + (i % DZ)] = W3g[i];
    for (int i = tid; i < DZ * HENC; i += NTHREADS) {
        int j = i / HENC, k = i % HENC;
        Wmus[j * 52 + k] = Wmug[i];
        Wlss[j * 52 + k] = Wlsg[i];
    }
    for (int i = tid; i < HENC; i += NTHREADS) b1s[i] = b1g[i];
    for (int i = tid; i < DZ; i += NTHREADS) { b2ms[i] = b2mug[i]; b2ls[i] = b2lsg[i]; }
    for (int i = tid; i < HDEC; i += NTHREADS) b3s[i] = b3g[i];
    for (int i = tid; i < DIMG; i += NTHREADS) { bmus[i] = bmudg[i]; blss[i] = blsdg[i]; }
    // (the __syncthreads inside the first GEMM1 chunk orders these fills before use)

    const int arow = warp * 16 + (lane >> 2);
    const int kk2  = (lane & 3) * 2;

    // ================= GEMM1: h = tanh(x @ W1^T + b1) =================
    float e[7][4];
#pragma unroll
    for (int f = 0; f < 7; f++)
#pragma unroll
        for (int c = 0; c < 4; c++) e[f][c] = 0.f;

    for (int ch = 0; ch < 7; ch++) {
        // load x chunk [128][112] fp32 -> bf16 smem [128][120]
        for (int i = tid; i < 3584; i += NTHREADS) {
            int r = i / 28, c = (i % 28) * 4;
            float4 v = *(const float4*)&x[(size_t)(row0 + r) * DIMG + ch * 112 + c];
            __nv_bfloat162* dst = (__nv_bfloat162*)&xs[r * 120 + c];
            dst[0] = __floats2bfloat162_rn(v.x, v.y);
            dst[1] = __floats2bfloat162_rn(v.z, v.w);
        }
        __syncthreads();
#pragma unroll
        for (int k7 = 0; k7 < 7; k7++) {
            int kb = k7 * 16;
            uint32_t a0 = *(const uint32_t*)&xs[arow * 120 + kb + kk2];
            uint32_t a1 = *(const uint32_t*)&xs[(arow + 8) * 120 + kb + kk2];
            uint32_t a2 = *(const uint32_t*)&xs[arow * 120 + kb + kk2 + 8];
            uint32_t a3 = *(const uint32_t*)&xs[(arow + 8) * 120 + kb + kk2 + 8];
#pragma unroll
            for (int f = 0; f < 7; f++) {
                int bn = f * 8 + (lane >> 2);
                uint32_t b0 = *(const uint32_t*)&W1s[bn * 792 + ch * 112 + kb + kk2];
                uint32_t b1 = *(const uint32_t*)&W1s[bn * 792 + ch * 112 + kb + kk2 + 8];
                mma16816(e[f], a0, a1, a2, a3, b0, b1);
            }
        }
        __syncthreads();
    }

    // GEMM1 epilogue -> h (fp32, pitch 52)
    {
        int r = arow;
#pragma unroll
        for (int f = 0; f < 7; f++) {
            int c = f * 8 + (lane & 3) * 2;
            if (c < 50) {
                float bc0 = b1s[c], bc1 = b1s[c + 1];
                hs[r * 52 + c]           = tanhf(e[f][0] + bc0);
                hs[r * 52 + c + 1]       = tanhf(e[f][1] + bc1);
                hs[(r + 8) * 52 + c]     = tanhf(e[f][2] + bc0);
                hs[(r + 8) * 52 + c + 1] = tanhf(e[f][3] + bc1);
            }
        }
    }
    for (int i = tid; i < TM * 2; i += NTHREADS) hs[(i >> 1) * 52 + 50 + (i & 1)] = 0.f;
    __syncthreads();

    // ================= encoder head + reparam (fp32 scalar) =================
    {
        int r = tid >> 1;
        int half = tid & 1;
        float4 hv[13];
#pragma unroll
        for (int i = 0; i < 13; i++) hv[i] = *(const float4*)&hs[r * 52 + i * 4];
        int jbeg = half ? 13 : 0;
        int jend = half ? 25 : 13;
        for (int j = jbeg; j < jend; j++) {
            float mu = b2ms[j];
            float ls = b2ls[j];
#pragma unroll
            for (int i = 0; i < 13; i++) {
                float4 wm = *(const float4*)&Wmus[j * 52 + i * 4];
                float4 wl = *(const float4*)&Wlss[j * 52 + i * 4];
                mu += hv[i].x * wm.x + hv[i].y * wm.y + hv[i].z * wm.z + hv[i].w * wm.w;
                ls += hv[i].x * wl.x + hv[i].y * wl.y + hv[i].z * wl.z + hv[i].w * wl.w;
            }
            zs[r * 28 + j] = mu + __expf(0.5f * ls) * epsz[(size_t)(row0 + r) * DZ + j];
        }
    }
    for (int i = tid; i < TM * 3; i += NTHREADS) zs[(i / 3) * 28 + 25 + (i % 3)] = 0.f;
    __syncthreads();

    // ================= hd = tanh(z @ W3^T + b3) (fp32 scalar -> bf16) =================
    {
        int r = tid >> 1;
        int ob = (tid & 1) * 50;
        float4 zv[7];
#pragma unroll
        for (int i = 0; i < 7; i++) zv[i] = *(const float4*)&zs[r * 28 + i * 4];
        for (int o = 0; o < 50; o++) {
            int oo = ob + o;
            float acc = b3s[oo];
#pragma unroll
            for (int i = 0; i < 7; i++) {
                float4 w = *(const float4*)&W3s[oo * 28 + i * 4];
                acc += zv[i].x * w.x + zv[i].y * w.y + zv[i].z * w.z + zv[i].w * w.w;
            }
            hds[r * 120 + oo] = __float2bfloat16(tanhf(acc));
        }
    }
    for (int i = tid; i < TM * 20; i += NTHREADS)
        hds[(i / 20) * 120 + 100 + (i % 20)] = __float2bfloat16(0.f);
    __syncthreads();

    // ================= decoder GEMM + fused epilogue (double-buffered B) =================
    uint32_t Ar[7][4];
#pragma unroll
    for (int k = 0; k < 7; k++) {
        int kb = k * 16;
        Ar[k][0] = *(const uint32_t*)&hds[arow * 120 + kb + kk2];
        Ar[k][1] = *(const uint32_t*)&hds[(arow + 8) * 120 + kb + kk2];
        Ar[k][2] = *(const uint32_t*)&hds[arow * 120 + kb + kk2 + 8];
        Ar[k][3] = *(const uint32_t*)&hds[(arow + 8) * 120 + kb + kk2 + 8];
    }

    const size_t r1g = (size_t)(row0 + arow) * DIMG;
    const size_t r2g = (size_t)(row0 + arow + 8) * DIMG;

    // prologue: load B tile 0 into buf0
    for (int i = tid; i < 448; i += NTHREADS) {
        uint4 v = *(const uint4*)&g_Wd[i * 8];
        int rr = (i * 8) / 112, cc = (i * 8) % 112;
        *(uint4*)&Bbuf0[rr * 120 + cc] = v;
    }
    __syncthreads();

    for (int blk = 0; blk < 49; blk++) {
        __nv_bfloat16* cur = (blk & 1) ? Bbuf1 : Bbuf0;
        __nv_bfloat16* nxt = (blk & 1) ? Bbuf0 : Bbuf1;

        // prefetch next B tile into the other buffer (overlaps with mma below)
        if (blk + 1 < 49) {
            for (int i = tid; i < 448; i += NTHREADS) {
                uint4 v = *(const uint4*)&g_Wd[(blk + 1) * 3584 + i * 8];
                int rr = (i * 8) / 112, cc = (i * 8) % 112;
                *(uint4*)&nxt[rr * 120 + cc] = v;
            }
        }

        // prefetch epsx for this block (consumed in epilogue, overlaps mma latency)
        int j0 = blk * 16 + (lane & 3) * 2;
        float2 e0 = *(const float2*)&epsx[r1g + j0];
        float2 e1 = *(const float2*)&epsx[r1g + j0 + 8];
        float2 e2 = *(const float2*)&epsx[r2g + j0];
        float2 e3 = *(const float2*)&epsx[r2g + j0 + 8];

        float acc[4][4];
#pragma unroll
        for (int f = 0; f < 4; f++)
#pragma unroll
            for (int c = 0; c < 4; c++) acc[f][c] = 0.f;

#pragma unroll
        for (int f = 0; f < 4; f++) {
            int bn = f * 8 + (lane >> 2);
#pragma unroll
            for (int k = 0; k < 7; k++) {
                int kb = k * 16;
                uint32_t b0 = *(const uint32_t*)&cur[bn * 120 + kb + kk2];
                uint32_t b1 = *(const uint32_t*)&cur[bn * 120 + kb + kk2 + 8];
                mma16816(acc[f], Ar[k][0], Ar[k][1], Ar[k][2], Ar[k][3], b0, b1);
            }
        }

        // epilogue: frags 0,1 = mu (cols j0..j0+1, j0+8..j0+9); frags 2,3 = ls (same cols)
        float bm0 = bmus[j0], bm1 = bmus[j0 + 1], bm8 = bmus[j0 + 8], bm9 = bmus[j0 + 9];
        float bl0 = blss[j0], bl1 = blss[j0 + 1], bl8 = blss[j0 + 8], bl9 = blss[j0 + 9];

        float2 o;
        o.x = (acc[0][0] + bm0) + __expf(0.5f * (acc[2][0] + bl0)) * e0.x;
        o.y = (acc[0][1] + bm1) + __expf(0.5f * (acc[2][1] + bl1)) * e0.y;
        *(float2*)&out[r1g + j0] = o;
        o.x = (acc[1][0] + bm8) + __expf(0.5f * (acc[3][0] + bl8)) * e1.x;
        o.y = (acc[1][1] + bm9) + __expf(0.5f * (acc[3][1] + bl9)) * e1.y;
        *(float2*)&out[r1g + j0 + 8] = o;
        o.x = (acc[0][2] + bm0) + __expf(0.5f * (acc[2][2] + bl0)) * e2.x;
        o.y = (acc[0][3] + bm1) + __expf(0.5f * (acc[2][3] + bl1)) * e2.y;
        *(float2*)&out[r2g + j0] = o;
        o.x = (acc[1][2] + bm8) + __expf(0.5f * (acc[3][2] + bl8)) * e3.x;
        o.y = (acc[1][3] + bm9) + __expf(0.5f * (acc[3][3] + bl9)) * e3.y;
        *(float2*)&out[r2g + j0 + 8] = o;

        __syncthreads();
    }
}

extern "C" void kernel_launch(void* const* d_in, const int* in_sizes, int n_in,
                              void* d_out, int out_size) {
    const float* x     = (const float*)d_in[0];
    const float* eps_z = (const float*)d_in[1];
    const float* eps_x = (const float*)d_in[2];
    const float* W_in_e = (const float*)d_in[3];
    const float* b_in_e = (const float*)d_in[4];
    const float* W_mu_e = (const float*)d_in[5];
    const float* b_mu_e = (const float*)d_in[6];
    const float* W_ls_e = (const float*)d_in[7];
    const float* b_ls_e = (const float*)d_in[8];
    const float* W_in_d = (const float*)d_in[9];
    const float* b_in_d = (const float*)d_in[10];
    const float* W_mu_d = (const float*)d_in[11];
    const float* b_mu_d = (const float*)d_in[12];
    const float* W_ls_d = (const float*)d_in[13];
    const float* b_ls_d = (const float*)d_in[14];
    float* out = (float*)d_out;

    int B = in_sizes[0] / DIMG;

    static_assert(SMEM_TOTAL <= 232448, "smem");
    cudaFuncSetAttribute(vae_fused, cudaFuncAttributeMaxDynamicSharedMemorySize, SMEM_TOTAL);

    // prep decoder weights (bf16, block-interleaved)
    prep_wd<<<(49 * 32 * 112 + 255) / 256, 256>>>(W_mu_d, W_ls_d);

    int grid = (B + TM - 1) / TM;
    vae_fused<<<grid, NTHREADS, SMEM_TOTAL>>>(
        x, eps_z, eps_x,
        W_in_e, b_in_e, W_mu_e, b_mu_e, W_ls_e, b_ls_e,
        W_in_d, b_in_d, b_mu_d, b_ls_d,
        out, B);
}

// round 5
// speedup vs baseline: 1.6607x; 1.6607x over previous
#include <cuda_runtime.h>
#include <cuda_bf16.h>
#include <cstdint>

#define DIMG 784
#define HENC 50
#define DZ   25
#define HDEC 100
#define TM   128
#define NT   256
#define BMAX 131072

// ---- device scratch (prepped weights + hd intermediate) ----
// Decoder weights, block-interleaved for mma B operand:
// 49 blocks x 32 rows (0..15 = W_mu_d[blk*16+r], 16..31 = W_ls_d) x 112 k (k>=100 zero)
__device__ __align__(16) __nv_bfloat16 g_Wd[49 * 32 * 112];
// Encoder W1 bf16, chunked: [7 ch][56 rows (>=50 zero)][112 k]
__device__ __align__(16) __nv_bfloat16 g_W1[7 * 56 * 112];
// hd intermediate: [B][112] bf16 (cols 100..111 zero)
__device__ __align__(16) __nv_bfloat16 g_hd[(size_t)BMAX * 112];

__global__ void prep_wd(const float* __restrict__ Wmu, const float* __restrict__ Wls) {
    int idx = blockIdx.x * 256 + threadIdx.x;
    if (idx >= 49 * 32 * 112) return;
    int k = idx % 112, r = (idx / 112) % 32, blk = idx / (112 * 32);
    float v = 0.f;
    if (k < 100) {
        int j = blk * 16 + (r & 15);
        v = (r < 16) ? Wmu[j * 100 + k] : Wls[j * 100 + k];
    }
    g_Wd[idx] = __float2bfloat16(v);
}

__global__ void prep_w1(const float* __restrict__ W1) {
    int idx = blockIdx.x * 256 + threadIdx.x;
    if (idx >= 7 * 56 * 112) return;
    int k = idx % 112, r = (idx / 112) % 56, ch = idx / (112 * 56);
    float v = (r < HENC) ? W1[r * DIMG + ch * 112 + k] : 0.f;
    g_W1[idx] = __float2bfloat16(v);
}

__device__ __forceinline__ void mma16816(float* d,
                                         uint32_t a0, uint32_t a1, uint32_t a2, uint32_t a3,
                                         uint32_t b0, uint32_t b1) {
    asm volatile(
        "mma.sync.aligned.m16n8k16.row.col.f32.bf16.bf16.f32 "
        "{%0,%1,%2,%3}, {%4,%5,%6,%7}, {%8,%9}, {%0,%1,%2,%3};\n"
        : "+f"(d[0]), "+f"(d[1]), "+f"(d[2]), "+f"(d[3])
        : "r"(a0), "r"(a1), "r"(a2), "r"(a3), "r"(b0), "r"(b1));
}

// ================= Kernel 1: encoder + reparam + decoder-in =================
// smem layout (bytes, 16-aligned)
#define E_XS  0       // x chunk bf16 [128][120] = 30720 ; later hd bf16 [128][120]
#define E_W1  30720   // W1 chunk bf16 [56][120] = 13440
#define E_HS  44160   // h fp32 [128][52] = 26624
#define E_ZS  70784   // z fp32 [128][28] = 14336
#define E_W3  85120   // W_in_d fp32 [100][28] = 11200
#define E_WMU 96320   // [25][52] = 5200
#define E_WLS 101520  // [25][52] = 5200
#define E_B1  106720  // 224
#define E_B2M 106944  // 112
#define E_B2L 107056  // 112
#define E_B3  107168  // 400 -> 107568
#define E_SMEM 107584

__global__ void __launch_bounds__(NT, 2) vae_enc(
    const float* __restrict__ x,    const float* __restrict__ epsz,
    const float* __restrict__ b1g,
    const float* __restrict__ Wmug, const float* __restrict__ b2mug,
    const float* __restrict__ Wlsg, const float* __restrict__ b2lsg,
    const float* __restrict__ W3g,  const float* __restrict__ b3g,
    int Btotal)
{
    extern __shared__ char sm[];
    __nv_bfloat16* xs   = (__nv_bfloat16*)(sm + E_XS);
    __nv_bfloat16* hds  = (__nv_bfloat16*)(sm + E_XS);   // alias after GEMM1
    __nv_bfloat16* W1b  = (__nv_bfloat16*)(sm + E_W1);
    float* hs   = (float*)(sm + E_HS);
    float* zs   = (float*)(sm + E_ZS);
    float* W3s  = (float*)(sm + E_W3);
    float* Wmus = (float*)(sm + E_WMU);
    float* Wlss = (float*)(sm + E_WLS);
    float* b1s  = (float*)(sm + E_B1);
    float* b2ms = (float*)(sm + E_B2M);
    float* b2ls = (float*)(sm + E_B2L);
    float* b3s  = (float*)(sm + E_B3);

    const int tid  = threadIdx.x;
    const int lane = tid & 31;
    const int warp = tid >> 5;
    const int row0 = blockIdx.x * TM;
    if (row0 >= Btotal) return;

    // zero padded region E_W3..end, then fill small weights/biases
    for (int i = tid; i < (E_SMEM - E_W3) / 16; i += NT)
        ((uint4*)(sm + E_W3))[i] = make_uint4(0, 0, 0, 0);
    __syncthreads();

    for (int i = tid; i < HDEC * DZ; i += NT) W3s[(i / DZ) * 28 + (i % DZ)] = W3g[i];
    for (int i = tid; i < DZ * HENC; i += NT) {
        int j = i / HENC, k = i % HENC;
        Wmus[j * 52 + k] = Wmug[i];
        Wlss[j * 52 + k] = Wlsg[i];
    }
    for (int i = tid; i < HENC; i += NT) b1s[i] = b1g[i];
    for (int i = tid; i < DZ; i += NT) { b2ms[i] = b2mug[i]; b2ls[i] = b2lsg[i]; }
    for (int i = tid; i < HDEC; i += NT) b3s[i] = b3g[i];
    // (covered by the sync inside the first GEMM1 chunk)

    const int arow = warp * 16 + (lane >> 2);
    const int kk2  = (lane & 3) * 2;

    // GEMM1: h = tanh(x @ W1^T + b1), K streamed in 7 chunks of 112
    float e[7][4];
#pragma unroll
    for (int f = 0; f < 7; f++)
#pragma unroll
        for (int c = 0; c < 4; c++) e[f][c] = 0.f;

    for (int ch = 0; ch < 7; ch++) {
        for (int i = tid; i < 3584; i += NT) {   // x chunk [128][112] fp32 -> bf16
            int r = i / 28, c = (i % 28) * 4;
            float4 v = *(const float4*)&x[(size_t)(row0 + r) * DIMG + ch * 112 + c];
            __nv_bfloat162* dst = (__nv_bfloat162*)&xs[r * 120 + c];
            dst[0] = __floats2bfloat162_rn(v.x, v.y);
            dst[1] = __floats2bfloat162_rn(v.z, v.w);
        }
        for (int i = tid; i < 784; i += NT) {    // W1 chunk [56][112] bf16
            uint4 v = *(const uint4*)&g_W1[ch * 6272 + i * 8];
            int rr = (i * 8) / 112, cc = (i * 8) % 112;
            *(uint4*)&W1b[rr * 120 + cc] = v;
        }
        __syncthreads();
#pragma unroll
        for (int k7 = 0; k7 < 7; k7++) {
            int kb = k7 * 16;
            uint32_t a0 = *(const uint32_t*)&xs[arow * 120 + kb + kk2];
            uint32_t a1 = *(const uint32_t*)&xs[(arow + 8) * 120 + kb + kk2];
            uint32_t a2 = *(const uint32_t*)&xs[arow * 120 + kb + kk2 + 8];
            uint32_t a3 = *(const uint32_t*)&xs[(arow + 8) * 120 + kb + kk2 + 8];
#pragma unroll
            for (int f = 0; f < 7; f++) {
                int bn = f * 8 + (lane >> 2);
                uint32_t b0 = *(const uint32_t*)&W1b[bn * 120 + kb + kk2];
                uint32_t b1 = *(const uint32_t*)&W1b[bn * 120 + kb + kk2 + 8];
                mma16816(e[f], a0, a1, a2, a3, b0, b1);
            }
        }
        __syncthreads();
    }

    // epilogue -> h fp32 (pitch 52)
    {
        int r = arow;
#pragma unroll
        for (int f = 0; f < 7; f++) {
            int c = f * 8 + (lane & 3) * 2;
            if (c < 50) {
                float bc0 = b1s[c], bc1 = b1s[c + 1];
                hs[r * 52 + c]           = tanhf(e[f][0] + bc0);
                hs[r * 52 + c + 1]       = tanhf(e[f][1] + bc1);
                hs[(r + 8) * 52 + c]     = tanhf(e[f][2] + bc0);
                hs[(r + 8) * 52 + c + 1] = tanhf(e[f][3] + bc1);
            }
        }
    }
    for (int i = tid; i < TM * 2; i += NT) hs[(i >> 1) * 52 + 50 + (i & 1)] = 0.f;
    __syncthreads();

    // encoder head + reparam (fp32 scalar)
    {
        int r = tid >> 1;
        int half = tid & 1;
        float4 hv[13];
#pragma unroll
        for (int i = 0; i < 13; i++) hv[i] = *(const float4*)&hs[r * 52 + i * 4];
        int jbeg = half ? 13 : 0;
        int jend = half ? 25 : 13;
        for (int j = jbeg; j < jend; j++) {
            float mu = b2ms[j];
            float ls = b2ls[j];
#pragma unroll
            for (int i = 0; i < 13; i++) {
                float4 wm = *(const float4*)&Wmus[j * 52 + i * 4];
                float4 wl = *(const float4*)&Wlss[j * 52 + i * 4];
                mu += hv[i].x * wm.x + hv[i].y * wm.y + hv[i].z * wm.z + hv[i].w * wm.w;
                ls += hv[i].x * wl.x + hv[i].y * wl.y + hv[i].z * wl.z + hv[i].w * wl.w;
            }
            zs[r * 28 + j] = mu + __expf(0.5f * ls) * epsz[(size_t)(row0 + r) * DZ + j];
        }
    }
    for (int i = tid; i < TM * 3; i += NT) zs[(i / 3) * 28 + 25 + (i % 3)] = 0.f;
    __syncthreads();

    // hd = tanh(z @ W3^T + b3) -> bf16 smem (pitch 120)
    {
        int r = tid >> 1;
        int ob = (tid & 1) * 50;
        float4 zv[7];
#pragma unroll
        for (int i = 0; i < 7; i++) zv[i] = *(const float4*)&zs[r * 28 + i * 4];
        for (int o = 0; o < 50; o++) {
            int oo = ob + o;
            float acc = b3s[oo];
#pragma unroll
            for (int i = 0; i < 7; i++) {
                float4 w = *(const float4*)&W3s[oo * 28 + i * 4];
                acc += zv[i].x * w.x + zv[i].y * w.y + zv[i].z * w.z + zv[i].w * w.w;
            }
            hds[r * 120 + oo] = __float2bfloat16(tanhf(acc));
        }
    }
    for (int i = tid; i < TM * 12; i += NT)   // zero cols 100..111 (read by decoder mma)
        hds[(i / 12) * 120 + 100 + (i % 12)] = __float2bfloat16(0.f);
    __syncthreads();

    // copy hd tile -> g_hd [row][112], vectorized
    for (int i = tid; i < 1792; i += NT) {
        int rr = (i * 8) / 112, cc = (i * 8) % 112;
        uint4 v = *(const uint4*)&hds[rr * 120 + cc];
        *(uint4*)&g_hd[(size_t)(row0 + rr) * 112 + cc] = v;
    }
}

// ================= Kernel 2: decoder GEMM + fused epilogue =================
#define D_HD  0       // hd bf16 [128][120] = 30720
#define D_BB0 30720   // B tile buf0 [32][120] = 7680
#define D_BB1 38400   // B tile buf1
#define D_BMU 46080   // fp32[784]
#define D_BLS 49216   // fp32[784]
#define D_SMEM 52352

__global__ void __launch_bounds__(NT, 3) vae_dec(
    const float* __restrict__ epsx,
    const float* __restrict__ bmudg, const float* __restrict__ blsdg,
    float* __restrict__ out, int Btotal)
{
    extern __shared__ char sm[];
    __nv_bfloat16* hd_s  = (__nv_bfloat16*)(sm + D_HD);
    __nv_bfloat16* Bbuf0 = (__nv_bfloat16*)(sm + D_BB0);
    __nv_bfloat16* Bbuf1 = (__nv_bfloat16*)(sm + D_BB1);
    float* bmus = (float*)(sm + D_BMU);
    float* blss = (float*)(sm + D_BLS);

    const int tid  = threadIdx.x;
    const int lane = tid & 31;
    const int warp = tid >> 5;
    const int row0 = blockIdx.x * TM;
    if (row0 >= Btotal) return;

    for (int i = tid; i < DIMG; i += NT) { bmus[i] = bmudg[i]; blss[i] = blsdg[i]; }

    // load hd tile [128][112] -> smem [128][120]
    for (int i = tid; i < 1792; i += NT) {
        uint4 v = *(const uint4*)&g_hd[(size_t)row0 * 112 + i * 8];
        int rr = (i * 8) / 112, cc = (i * 8) % 112;
        *(uint4*)&hd_s[rr * 120 + cc] = v;
    }
    // prologue: B tile 0 -> buf0
    for (int i = tid; i < 448; i += NT) {
        uint4 v = *(const uint4*)&g_Wd[i * 8];
        int rr = (i * 8) / 112, cc = (i * 8) % 112;
        *(uint4*)&Bbuf0[rr * 120 + cc] = v;
    }
    __syncthreads();

    const int arow = warp * 16 + (lane >> 2);
    const int kk2  = (lane & 3) * 2;

    uint32_t Ar[7][4];
#pragma unroll
    for (int k = 0; k < 7; k++) {
        int kb = k * 16;
        Ar[k][0] = *(const uint32_t*)&hd_s[arow * 120 + kb + kk2];
        Ar[k][1] = *(const uint32_t*)&hd_s[(arow + 8) * 120 + kb + kk2];
        Ar[k][2] = *(const uint32_t*)&hd_s[arow * 120 + kb + kk2 + 8];
        Ar[k][3] = *(const uint32_t*)&hd_s[(arow + 8) * 120 + kb + kk2 + 8];
    }

    const size_t r1g = (size_t)(row0 + arow) * DIMG;
    const size_t r2g = (size_t)(row0 + arow + 8) * DIMG;

    for (int blk = 0; blk < 49; blk++) {
        __nv_bfloat16* cur = (blk & 1) ? Bbuf1 : Bbuf0;
        __nv_bfloat16* nxt = (blk & 1) ? Bbuf0 : Bbuf1;

        if (blk + 1 < 49) {
            for (int i = tid; i < 448; i += NT) {
                uint4 v = *(const uint4*)&g_Wd[(blk + 1) * 3584 + i * 8];
                int rr = (i * 8) / 112, cc = (i * 8) % 112;
                *(uint4*)&nxt[rr * 120 + cc] = v;
            }
        }

        int j0 = blk * 16 + (lane & 3) * 2;
        float2 e0 = *(const float2*)&epsx[r1g + j0];
        float2 e1 = *(const float2*)&epsx[r1g + j0 + 8];
        float2 e2 = *(const float2*)&epsx[r2g + j0];
        float2 e3 = *(const float2*)&epsx[r2g + j0 + 8];

        float acc[4][4];
#pragma unroll
        for (int f = 0; f < 4; f++)
#pragma unroll
            for (int c = 0; c < 4; c++) acc[f][c] = 0.f;

#pragma unroll
        for (int f = 0; f < 4; f++) {
            int bn = f * 8 + (lane >> 2);
#pragma unroll
            for (int k = 0; k < 7; k++) {
                int kb = k * 16;
                uint32_t b0 = *(const uint32_t*)&cur[bn * 120 + kb + kk2];
                uint32_t b1 = *(const uint32_t*)&cur[bn * 120 + kb + kk2 + 8];
                mma16816(acc[f], Ar[k][0], Ar[k][1], Ar[k][2], Ar[k][3], b0, b1);
            }
        }

        float bm0 = bmus[j0], bm1 = bmus[j0 + 1], bm8 = bmus[j0 + 8], bm9 = bmus[j0 + 9];
        float bl0 = blss[j0], bl1 = blss[j0 + 1], bl8 = blss[j0 + 8], bl9 = blss[j0 + 9];

        float2 o;
        o.x = (acc[0][0] + bm0) + __expf(0.5f * (acc[2][0] + bl0)) * e0.x;
        o.y = (acc[0][1] + bm1) + __expf(0.5f * (acc[2][1] + bl1)) * e0.y;
        *(float2*)&out[r1g + j0] = o;
        o.x = (acc[1][0] + bm8) + __expf(0.5f * (acc[3][0] + bl8)) * e1.x;
        o.y = (acc[1][1] + bm9) + __expf(0.5f * (acc[3][1] + bl9)) * e1.y;
        *(float2*)&out[r1g + j0 + 8] = o;
        o.x = (acc[0][2] + bm0) + __expf(0.5f * (acc[2][2] + bl0)) * e2.x;
        o.y = (acc[0][3] + bm1) + __expf(0.5f * (acc[2][3] + bl1)) * e2.y;
        *(float2*)&out[r2g + j0] = o;
        o.x = (acc[1][2] + bm8) + __expf(0.5f * (acc[3][2] + bl8)) * e3.x;
        o.y = (acc[1][3] + bm9) + __expf(0.5f * (acc[3][3] + bl9)) * e3.y;
        *(float2*)&out[r2g + j0 + 8] = o;

        __syncthreads();
    }
}

extern "C" void kernel_launch(void* const* d_in, const int* in_sizes, int n_in,
                              void* d_out, int out_size) {
    const float* x      = (const float*)d_in[0];
    const float* eps_z  = (const float*)d_in[1];
    const float* eps_x  = (const float*)d_in[2];
    const float* W_in_e = (const float*)d_in[3];
    const float* b_in_e = (const float*)d_in[4];
    const float* W_mu_e = (const float*)d_in[5];
    const float* b_mu_e = (const float*)d_in[6];
    const float* W_ls_e = (const float*)d_in[7];
    const float* b_ls_e = (const float*)d_in[8];
    const float* W_in_d = (const float*)d_in[9];
    const float* b_in_d = (const float*)d_in[10];
    const float* W_mu_d = (const float*)d_in[11];
    const float* b_mu_d = (const float*)d_in[12];
    const float* W_ls_d = (const float*)d_in[13];
    const float* b_ls_d = (const float*)d_in[14];
    float* out = (float*)d_out;

    int B = in_sizes[0] / DIMG;
    int grid = (B + TM - 1) / TM;

    cudaFuncSetAttribute(vae_enc, cudaFuncAttributeMaxDynamicSharedMemorySize, E_SMEM);
    cudaFuncSetAttribute(vae_dec, cudaFuncAttributeMaxDynamicSharedMemorySize, D_SMEM);

    prep_wd<<<(49 * 32 * 112 + 255) / 256, 256>>>(W_mu_d, W_ls_d);
    prep_w1<<<(7 * 56 * 112 + 255) / 256, 256>>>(W_in_e);

    vae_enc<<<grid, NT, E_SMEM>>>(x, eps_z, b_in_e,
                                  W_mu_e, b_mu_e, W_ls_e, b_ls_e,
                                  W_in_d, b_in_d, B);
    vae_dec<<<grid, NT, D_SMEM>>>(eps_x, b_mu_d, b_ls_d, out, B);
}